// round 6
// baseline (speedup 1.0000x reference)
#include <cuda_runtime.h>
#include <cuda_bf16.h>
#include <math.h>

// Problem constants
#define B_ 2
#define L_ 2048
#define D_ 1024
#define F_ 4096
#define H_ 16
#define HD_ 64
#define M_ (B_ * L_)          // 4096 rows of tokens
#define LN_EPS 1e-6f

// ---------------------------------------------------------------------------
// Scratch (static device globals; no allocation anywhere)
// ---------------------------------------------------------------------------
__device__ float g_h[M_ * D_];        // layernorm output (reused for ln1 and ln2)
__device__ float g_qkv[M_ * 3 * D_];  // qkv projection
__device__ float g_attn[M_ * D_];     // attention output (pre-proj)
__device__ float g_x1[M_ * D_];       // residual stream after attention
__device__ float g_mid[M_ * F_];      // MLP hidden

// ---------------------------------------------------------------------------
// LayerNorm: one block per row (D=1024, 256 threads -> one float4 per thread)
// ---------------------------------------------------------------------------
__global__ __launch_bounds__(256) void layernorm_k(
    const float* __restrict__ x, const float* __restrict__ gamma,
    const float* __restrict__ beta, float* __restrict__ out)
{
    const int row = blockIdx.x;
    const int t = threadIdx.x;
    const float4 v = *(const float4*)(x + (size_t)row * D_ + t * 4);

    float s = v.x + v.y + v.z + v.w;
    float q = v.x * v.x + v.y * v.y + v.z * v.z + v.w * v.w;

    #pragma unroll
    for (int off = 16; off > 0; off >>= 1) {
        s += __shfl_down_sync(0xffffffffu, s, off);
        q += __shfl_down_sync(0xffffffffu, q, off);
    }
    __shared__ float ss[8], qq[8];
    const int wid = t >> 5, lane = t & 31;
    if (lane == 0) { ss[wid] = s; qq[wid] = q; }
    __syncthreads();
    if (t == 0) {
        float S = 0.f, Q = 0.f;
        #pragma unroll
        for (int i = 0; i < 8; i++) { S += ss[i]; Q += qq[i]; }
        ss[0] = S; qq[0] = Q;
    }
    __syncthreads();
    const float mu = ss[0] * (1.0f / D_);
    const float var = qq[0] * (1.0f / D_) - mu * mu;
    const float rstd = rsqrtf(var + LN_EPS);

    const float4 g4 = *(const float4*)(gamma + t * 4);
    const float4 b4 = *(const float4*)(beta + t * 4);
    float4 o;
    o.x = (v.x - mu) * rstd * g4.x + b4.x;
    o.y = (v.y - mu) * rstd * g4.y + b4.y;
    o.z = (v.z - mu) * rstd * g4.z + b4.z;
    o.w = (v.w - mu) * rstd * g4.w + b4.w;
    *(float4*)(out + (size_t)row * D_ + t * 4) = o;
}

// ---------------------------------------------------------------------------
// SGEMM: C[M,N] = A[M,K] @ B[K,N] (+ bias) (+ gelu) (+ residual)
// 128x128 tile, BK=8, 256 threads, 8x8 per thread.
// EPI: 0 = none, 1 = bias + residual, 2 = bias + gelu
// ---------------------------------------------------------------------------
__device__ __forceinline__ float gelu_tanh(float v) {
    const float c = 0.7978845608028654f;
    float u = c * (v + 0.044715f * v * v * v);
    return 0.5f * v * (1.0f + tanhf(u));
}

template <int EPI>
__global__ __launch_bounds__(256) void sgemm128(
    const float* __restrict__ A, const float* __restrict__ Bm,
    const float* __restrict__ bias, const float* __restrict__ res,
    float* __restrict__ C, int M, int N, int K)
{
    __shared__ float As[8][128];
    __shared__ float Bs[8][128];

    const int tid = threadIdx.x;
    const int mBase = blockIdx.y * 128;
    const int nBase = blockIdx.x * 128;

    const int aRow = tid >> 1;          // 0..127
    const int aCol = (tid & 1) * 4;     // 0 or 4
    const int bRow = tid >> 5;          // 0..7
    const int bCol = (tid & 31) * 4;    // 0..124

    const float* Aptr = A + (size_t)(mBase + aRow) * K + aCol;
    const float* Bptr = Bm + (size_t)bRow * N + nBase + bCol;

    const int tx = tid & 15;            // 0..15 -> N sub-tile
    const int ty = tid >> 4;            // 0..15 -> M sub-tile

    float acc[8][8];
    #pragma unroll
    for (int i = 0; i < 8; i++)
        #pragma unroll
        for (int j = 0; j < 8; j++) acc[i][j] = 0.f;

    for (int k0 = 0; k0 < K; k0 += 8) {
        const float4 a4 = *(const float4*)(Aptr + k0);
        const float4 b4 = *(const float4*)(Bptr + (size_t)k0 * N);
        As[aCol + 0][aRow] = a4.x;
        As[aCol + 1][aRow] = a4.y;
        As[aCol + 2][aRow] = a4.z;
        As[aCol + 3][aRow] = a4.w;
        *(float4*)&Bs[bRow][bCol] = b4;
        __syncthreads();

        #pragma unroll
        for (int k = 0; k < 8; k++) {
            const float4 a0 = *(const float4*)&As[k][ty * 8];
            const float4 a1 = *(const float4*)&As[k][ty * 8 + 4];
            const float4 b0 = *(const float4*)&Bs[k][tx * 8];
            const float4 b1 = *(const float4*)&Bs[k][tx * 8 + 4];
            const float ar[8] = {a0.x, a0.y, a0.z, a0.w, a1.x, a1.y, a1.z, a1.w};
            const float br[8] = {b0.x, b0.y, b0.z, b0.w, b1.x, b1.y, b1.z, b1.w};
            #pragma unroll
            for (int i = 0; i < 8; i++)
                #pragma unroll
                for (int j = 0; j < 8; j++)
                    acc[i][j] = fmaf(ar[i], br[j], acc[i][j]);
        }
        __syncthreads();
    }

    // Epilogue
    #pragma unroll
    for (int i = 0; i < 8; i++) {
        const int m = mBase + ty * 8 + i;
        #pragma unroll
        for (int jj = 0; jj < 8; jj += 4) {
            const int n = nBase + tx * 8 + jj;
            float4 c = make_float4(acc[i][jj], acc[i][jj + 1],
                                   acc[i][jj + 2], acc[i][jj + 3]);
            if (EPI == 1 || EPI == 2) {
                const float4 bi = *(const float4*)(bias + n);
                c.x += bi.x; c.y += bi.y; c.z += bi.z; c.w += bi.w;
            }
            if (EPI == 2) {
                c.x = gelu_tanh(c.x); c.y = gelu_tanh(c.y);
                c.z = gelu_tanh(c.z); c.w = gelu_tanh(c.w);
            }
            if (EPI == 1) {
                const float4 r = *(const float4*)(res + (size_t)m * N + n);
                c.x += r.x; c.y += r.y; c.z += r.z; c.w += r.w;
            }
            *(float4*)(C + (size_t)m * N + n) = c;
        }
    }
}

// ---------------------------------------------------------------------------
// Flash attention (fp32, online softmax). 64 queries x 64 keys per tile,
// hd=64. Grid (L/64, H, B). 256 threads: (ty=tid/16 rows, tx=tid%16 cols),
// each thread owns a 4x4 patch. Reads q/k/v directly out of g_qkv.
// ---------------------------------------------------------------------------
#define FA_STRIDE 68
#define FA_BUF (64 * FA_STRIDE)
#define FA_SMEM (4 * FA_BUF * 4)

__global__ __launch_bounds__(256) void flash_attn_k(
    const float* __restrict__ qkv, float* __restrict__ out)
{
    extern __shared__ float sm[];
    float* Qt = sm;               // [d][m] d-major, stride 68
    float* Kt = Qt + FA_BUF;      // [d][n]
    float* Vs = Kt + FA_BUF;      // [n][d]
    float* Ps = Vs + FA_BUF;      // [m][n]

    const int b = blockIdx.z;
    const int h = blockIdx.y;
    const int qb = blockIdx.x * 64;
    const int t = threadIdx.x;
    const int tm = t >> 4;        // 0..15
    const int tn = t & 15;        // 0..15

    // load Q tile (transposed into Qt[d][m])
    for (int idx = t; idx < 64 * 16; idx += 256) {
        const int m = idx >> 4;
        const int d4 = (idx & 15) * 4;
        const float4 v = *(const float4*)(
            qkv + (size_t)(b * L_ + qb + m) * (3 * D_) + h * HD_ + d4);
        Qt[(d4 + 0) * FA_STRIDE + m] = v.x;
        Qt[(d4 + 1) * FA_STRIDE + m] = v.y;
        Qt[(d4 + 2) * FA_STRIDE + m] = v.z;
        Qt[(d4 + 3) * FA_STRIDE + m] = v.w;
    }

    float mo[4] = {-INFINITY, -INFINITY, -INFINITY, -INFINITY};
    float lo[4] = {0.f, 0.f, 0.f, 0.f};
    float acc[4][4];
    #pragma unroll
    for (int i = 0; i < 4; i++)
        #pragma unroll
        for (int j = 0; j < 4; j++) acc[i][j] = 0.f;

    __syncthreads();

    for (int kb = 0; kb < L_; kb += 64) {
        // load K (transposed) and V tiles
        for (int idx = t; idx < 64 * 16; idx += 256) {
            const int n = idx >> 4;
            const int d4 = (idx & 15) * 4;
            const float* kp = qkv + (size_t)(b * L_ + kb + n) * (3 * D_)
                              + D_ + h * HD_ + d4;
            const float4 kv = *(const float4*)kp;
            Kt[(d4 + 0) * FA_STRIDE + n] = kv.x;
            Kt[(d4 + 1) * FA_STRIDE + n] = kv.y;
            Kt[(d4 + 2) * FA_STRIDE + n] = kv.z;
            Kt[(d4 + 3) * FA_STRIDE + n] = kv.w;
            *(float4*)&Vs[n * FA_STRIDE + d4] = *(const float4*)(kp + D_);
        }
        __syncthreads();

        // S = Q K^T * 0.125
        float s[4][4];
        #pragma unroll
        for (int i = 0; i < 4; i++)
            #pragma unroll
            for (int j = 0; j < 4; j++) s[i][j] = 0.f;
        #pragma unroll 4
        for (int k = 0; k < HD_; k++) {
            const float4 q4 = *(const float4*)&Qt[k * FA_STRIDE + tm * 4];
            const float4 k4 = *(const float4*)&Kt[k * FA_STRIDE + tn * 4];
            const float qr[4] = {q4.x, q4.y, q4.z, q4.w};
            const float kr[4] = {k4.x, k4.y, k4.z, k4.w};
            #pragma unroll
            for (int i = 0; i < 4; i++)
                #pragma unroll
                for (int j = 0; j < 4; j++)
                    s[i][j] = fmaf(qr[i], kr[j], s[i][j]);
        }

        // online softmax per row (16-lane reduction across tn; tn occupies
        // the low 4 lane bits so xor 1/2/4/8 stays within the row group)
        #pragma unroll
        for (int i = 0; i < 4; i++) {
            float tmax = -INFINITY;
            #pragma unroll
            for (int j = 0; j < 4; j++) {
                s[i][j] *= 0.125f;
                tmax = fmaxf(tmax, s[i][j]);
            }
            #pragma unroll
            for (int off = 8; off > 0; off >>= 1)
                tmax = fmaxf(tmax, __shfl_xor_sync(0xffffffffu, tmax, off));

            const float mnew = fmaxf(mo[i], tmax);
            const float corr = __expf(mo[i] - mnew);
            float rs = 0.f;
            #pragma unroll
            for (int j = 0; j < 4; j++) {
                const float p = __expf(s[i][j] - mnew);
                Ps[(tm * 4 + i) * FA_STRIDE + tn * 4 + j] = p;
                rs += p;
            }
            #pragma unroll
            for (int off = 8; off > 0; off >>= 1)
                rs += __shfl_xor_sync(0xffffffffu, rs, off);

            lo[i] = lo[i] * corr + rs;
            mo[i] = mnew;
            #pragma unroll
            for (int j = 0; j < 4; j++) acc[i][j] *= corr;
        }
        __syncthreads();

        // acc += P @ V
        #pragma unroll 4
        for (int kk = 0; kk < 64; kk++) {
            const float4 v4 = *(const float4*)&Vs[kk * FA_STRIDE + tn * 4];
            const float vr[4] = {v4.x, v4.y, v4.z, v4.w};
            #pragma unroll
            for (int i = 0; i < 4; i++) {
                const float p = Ps[(tm * 4 + i) * FA_STRIDE + kk];
                #pragma unroll
                for (int j = 0; j < 4; j++)
                    acc[i][j] = fmaf(p, vr[j], acc[i][j]);
            }
        }
        __syncthreads();
    }

    // write normalized output: out[b][l][h*64+d]
    #pragma unroll
    for (int i = 0; i < 4; i++) {
        const float inv = 1.0f / lo[i];
        float4 o = make_float4(acc[i][0] * inv, acc[i][1] * inv,
                               acc[i][2] * inv, acc[i][3] * inv);
        *(float4*)(out + (size_t)(b * L_ + qb + tm * 4 + i) * D_
                   + h * HD_ + tn * 4) = o;
    }
}

// ---------------------------------------------------------------------------
// Launch
// ---------------------------------------------------------------------------
extern "C" void kernel_launch(void* const* d_in, const int* in_sizes, int n_in,
                              void* d_out, int out_size)
{
    const float* x      = (const float*)d_in[0];
    const float* ln1_s  = (const float*)d_in[1];
    const float* ln1_b  = (const float*)d_in[2];
    const float* w_qkv  = (const float*)d_in[3];
    const float* w_proj = (const float*)d_in[4];
    const float* b_proj = (const float*)d_in[5];
    const float* ln2_s  = (const float*)d_in[6];
    const float* ln2_b  = (const float*)d_in[7];
    const float* w_mlp1 = (const float*)d_in[8];
    const float* b_mlp1 = (const float*)d_in[9];
    const float* w_mlp2 = (const float*)d_in[10];
    const float* b_mlp2 = (const float*)d_in[11];
    float* out = (float*)d_out;

    float *h, *qkv, *attn, *x1, *mid;
    cudaGetSymbolAddress((void**)&h, g_h);
    cudaGetSymbolAddress((void**)&qkv, g_qkv);
    cudaGetSymbolAddress((void**)&attn, g_attn);
    cudaGetSymbolAddress((void**)&x1, g_x1);
    cudaGetSymbolAddress((void**)&mid, g_mid);

    static bool attr_set = false;
    if (!attr_set) {
        cudaFuncSetAttribute(flash_attn_k,
                             cudaFuncAttributeMaxDynamicSharedMemorySize,
                             FA_SMEM);
        attr_set = true;
    }

    // 1) pre-norm 1
    layernorm_k<<<M_, 256>>>(x, ln1_s, ln1_b, h);
    // 2) qkv projection (no bias)
    sgemm128<0><<<dim3(3 * D_ / 128, M_ / 128), 256>>>(
        h, w_qkv, nullptr, nullptr, qkv, M_, 3 * D_, D_);
    // 3) attention
    flash_attn_k<<<dim3(L_ / 64, H_, B_), 256, FA_SMEM>>>(qkv, attn);
    // 4) output projection + bias + residual
    sgemm128<1><<<dim3(D_ / 128, M_ / 128), 256>>>(
        attn, w_proj, b_proj, x, x1, M_, D_, D_);
    // 5) pre-norm 2
    layernorm_k<<<M_, 256>>>(x1, ln2_s, ln2_b, h);
    // 6) MLP up + bias + gelu
    sgemm128<2><<<dim3(F_ / 128, M_ / 128), 256>>>(
        h, w_mlp1, b_mlp1, nullptr, mid, M_, F_, D_);
    // 7) MLP down + bias + residual -> final output
    sgemm128<1><<<dim3(D_ / 128, M_ / 128), 256>>>(
        mid, w_mlp2, b_mlp2, x1, out, M_, D_, F_);
}

// round 8
// speedup vs baseline: 1.5031x; 1.5031x over previous
#include <cuda_runtime.h>
#include <cuda_bf16.h>
#include <mma.h>
#include <math.h>
#include <stdint.h>

using namespace nvcuda;

// Problem constants
#define B_ 2
#define L_ 2048
#define D_ 1024
#define F_ 4096
#define H_ 16
#define HD_ 64
#define M_ (B_ * L_)
#define LN_EPS 1e-6f

// ---------------------------------------------------------------------------
// Scratch (static device globals; no allocation anywhere)
// ---------------------------------------------------------------------------
__device__ __nv_bfloat16 g_h_hi[M_ * D_];
__device__ __nv_bfloat16 g_h_lo[M_ * D_];
__device__ float         g_qkv[M_ * 3 * D_];
__device__ __nv_bfloat16 g_at_hi[M_ * D_];
__device__ __nv_bfloat16 g_at_lo[M_ * D_];
__device__ float         g_x1[M_ * D_];
__device__ __nv_bfloat16 g_mid_hi[M_ * F_];
__device__ __nv_bfloat16 g_mid_lo[M_ * F_];
// weights transposed to [N][K], split hi/lo
__device__ __nv_bfloat16 g_wqkv_hi[3 * D_ * D_];
__device__ __nv_bfloat16 g_wqkv_lo[3 * D_ * D_];
__device__ __nv_bfloat16 g_wpr_hi[D_ * D_];
__device__ __nv_bfloat16 g_wpr_lo[D_ * D_];
__device__ __nv_bfloat16 g_wm1_hi[F_ * D_];
__device__ __nv_bfloat16 g_wm1_lo[F_ * D_];
__device__ __nv_bfloat16 g_wm2_hi[D_ * F_];
__device__ __nv_bfloat16 g_wm2_lo[D_ * F_];

// ---------------------------------------------------------------------------
// helpers
// ---------------------------------------------------------------------------
__device__ __forceinline__ uint32_t smem_to_u32(const void* p) {
    uint32_t a;
    asm("{ .reg .u64 t; cvta.to.shared.u64 t, %1; cvt.u32.u64 %0, t; }"
        : "=r"(a) : "l"(p));
    return a;
}

__device__ __forceinline__ void cp16(uint32_t daddr, const void* g) {
    asm volatile("cp.async.cg.shared.global [%0], [%1], 16;"
                 :: "r"(daddr), "l"(g));
}
#define CP_COMMIT() asm volatile("cp.async.commit_group;" ::: "memory")
#define CP_WAIT_ALL() asm volatile("cp.async.wait_group 0;" ::: "memory")

__device__ __forceinline__ uint32_t bf2u(__nv_bfloat16 a, __nv_bfloat16 b) {
    return (uint32_t)__bfloat16_as_ushort(a) |
           ((uint32_t)__bfloat16_as_ushort(b) << 16);
}

__device__ __forceinline__ void split_store4(
    __nv_bfloat16* __restrict__ hi, __nv_bfloat16* __restrict__ lo,
    size_t off, float a, float b, float c, float d)
{
    __nv_bfloat16 h0 = __float2bfloat16(a), h1 = __float2bfloat16(b);
    __nv_bfloat16 h2 = __float2bfloat16(c), h3 = __float2bfloat16(d);
    __nv_bfloat16 l0 = __float2bfloat16(a - __bfloat162float(h0));
    __nv_bfloat16 l1 = __float2bfloat16(b - __bfloat162float(h1));
    __nv_bfloat16 l2 = __float2bfloat16(c - __bfloat162float(h2));
    __nv_bfloat16 l3 = __float2bfloat16(d - __bfloat162float(h3));
    *(uint2*)(hi + off) = make_uint2(bf2u(h0, h1), bf2u(h2, h3));
    *(uint2*)(lo + off) = make_uint2(bf2u(l0, l1), bf2u(l2, l3));
}

__device__ __forceinline__ float gelu_tanh(float v) {
    const float c = 0.7978845608028654f;
    float u = c * (v + 0.044715f * v * v * v);
    return 0.5f * v * (1.0f + tanhf(u));
}

// ---------------------------------------------------------------------------
// Weight transpose + split: W[K][N] -> hi/lo[N][K] bf16
// ---------------------------------------------------------------------------
__global__ __launch_bounds__(256) void wsplit_t(
    const float* __restrict__ W, __nv_bfloat16* __restrict__ hi,
    __nv_bfloat16* __restrict__ lo, int K, int N)
{
    __shared__ float t[32][33];
    const int n0 = blockIdx.x * 32, k0 = blockIdx.y * 32;
    const int tx = threadIdx.x, ty = threadIdx.y;
    #pragma unroll
    for (int i = ty; i < 32; i += 8)
        t[i][tx] = W[(size_t)(k0 + i) * N + n0 + tx];
    __syncthreads();
    #pragma unroll
    for (int i = ty; i < 32; i += 8) {
        const float v = t[tx][i];                 // W[k0+tx][n0+i]
        const __nv_bfloat16 h = __float2bfloat16(v);
        const __nv_bfloat16 l = __float2bfloat16(v - __bfloat162float(h));
        const size_t o = (size_t)(n0 + i) * K + k0 + tx;
        hi[o] = h; lo[o] = l;
    }
}

// ---------------------------------------------------------------------------
// LayerNorm -> bf16 hi/lo
// ---------------------------------------------------------------------------
__global__ __launch_bounds__(256) void layernorm_k(
    const float* __restrict__ x, const float* __restrict__ gamma,
    const float* __restrict__ beta,
    __nv_bfloat16* __restrict__ ohi, __nv_bfloat16* __restrict__ olo)
{
    const int row = blockIdx.x;
    const int t = threadIdx.x;
    const float4 v = *(const float4*)(x + (size_t)row * D_ + t * 4);

    float s = v.x + v.y + v.z + v.w;
    float q = v.x * v.x + v.y * v.y + v.z * v.z + v.w * v.w;
    #pragma unroll
    for (int off = 16; off > 0; off >>= 1) {
        s += __shfl_down_sync(0xffffffffu, s, off);
        q += __shfl_down_sync(0xffffffffu, q, off);
    }
    __shared__ float ss[8], qq[8];
    const int wid = t >> 5, lane = t & 31;
    if (lane == 0) { ss[wid] = s; qq[wid] = q; }
    __syncthreads();
    if (t == 0) {
        float S = 0.f, Q = 0.f;
        #pragma unroll
        for (int i = 0; i < 8; i++) { S += ss[i]; Q += qq[i]; }
        ss[0] = S; qq[0] = Q;
    }
    __syncthreads();
    const float mu = ss[0] * (1.0f / D_);
    const float var = qq[0] * (1.0f / D_) - mu * mu;
    const float rstd = rsqrtf(var + LN_EPS);

    const float4 g4 = *(const float4*)(gamma + t * 4);
    const float4 b4 = *(const float4*)(beta + t * 4);
    const float ox = (v.x - mu) * rstd * g4.x + b4.x;
    const float oy = (v.y - mu) * rstd * g4.y + b4.y;
    const float oz = (v.z - mu) * rstd * g4.z + b4.z;
    const float ow = (v.w - mu) * rstd * g4.w + b4.w;
    split_store4(ohi, olo, (size_t)row * D_ + t * 4, ox, oy, oz, ow);
}

// ---------------------------------------------------------------------------
// WMMA GEMM: C[M,N] = (Ahi+Alo)[M,K] @ (Bhi+Blo)[N,K]^T  (bf16x3, fp32 acc)
// 128x128 tile, BK=32, 256 threads (8 warps, 2x4 of 64x32), cp.async 2-stage.
// EPI: 0 = fp32 out, 1 = +bias +residual -> fp32, 2 = +bias +gelu -> bf16 hi/lo
// ---------------------------------------------------------------------------
#define BM 128
#define BN 128
#define BK 32
#define LDS_ 40                          // smem ld (elements), 80B rows
#define TILE_EL (128 * LDS_)             // 5120 elements per operand tile
#define STAGE_EL (4 * TILE_EL)           // Ahi, Alo, Bhi, Blo
#define GEMM_SMEM (2 * STAGE_EL * 2)     // 81920 bytes (also covers epilogue sf)

template <int EPI>
__global__ __launch_bounds__(256, 1) void wm_gemm(
    const __nv_bfloat16* __restrict__ Ahi, const __nv_bfloat16* __restrict__ Alo,
    const __nv_bfloat16* __restrict__ Bhi, const __nv_bfloat16* __restrict__ Blo,
    const float* __restrict__ bias, const float* __restrict__ res,
    float* __restrict__ C, __nv_bfloat16* __restrict__ Chi,
    __nv_bfloat16* __restrict__ Clo, int M, int N, int K)
{
    extern __shared__ char smem[];
    __nv_bfloat16* sb = (__nv_bfloat16*)smem;
    const uint32_t sbase = smem_to_u32(smem);
    const int tid = threadIdx.x;
    const int w = tid >> 5;
    const int wm = w >> 2;                // 0..1
    const int wn = w & 3;                 // 0..3
    const int mBase = blockIdx.y * BM;
    const int nBase = blockIdx.x * BN;

    const __nv_bfloat16* gsrc[4] = {
        Ahi + (size_t)mBase * K,
        Alo + (size_t)mBase * K,
        Bhi + (size_t)nBase * K,
        Blo + (size_t)nBase * K };

    wmma::fragment<wmma::accumulator, 16, 16, 16, float> acc[4][2];
    #pragma unroll
    for (int i = 0; i < 4; i++)
        #pragma unroll
        for (int j = 0; j < 2; j++)
            wmma::fill_fragment(acc[i][j], 0.0f);

    const int nchunks = K / BK;

    // stage loader: 4 tiles x 128 rows x 32 cols bf16 -> 2048 16B copies
    auto load_stage = [&](int stg, int k0) {
        const uint32_t so = sbase + (uint32_t)stg * STAGE_EL * 2;
        #pragma unroll
        for (int it = 0; it < 8; it++) {
            const int idx = it * 256 + tid;       // 0..2047
            const int t4 = idx >> 9;              // tile 0..3
            const int r = (idx >> 2) & 127;       // row
            const int seg = idx & 3;              // 8-elem segment
            cp16(so + (uint32_t)(t4 * TILE_EL + r * LDS_ + seg * 8) * 2,
                 gsrc[t4] + (size_t)r * K + k0 + seg * 8);
        }
    };

    load_stage(0, 0);
    CP_COMMIT();

    for (int c = 0; c < nchunks; c++) {
        CP_WAIT_ALL();
        __syncthreads();
        if (c + 1 < nchunks) {
            load_stage((c + 1) & 1, (c + 1) * BK);
            CP_COMMIT();
        }
        const __nv_bfloat16* sAh = sb + (c & 1) * STAGE_EL;
        const __nv_bfloat16* sAl = sAh + TILE_EL;
        const __nv_bfloat16* sBh = sAh + 2 * TILE_EL;
        const __nv_bfloat16* sBl = sAh + 3 * TILE_EL;

        #pragma unroll
        for (int kk = 0; kk < BK; kk += 16) {
            wmma::fragment<wmma::matrix_a, 16, 16, 16, __nv_bfloat16,
                           wmma::row_major> ah[4], al[4];
            wmma::fragment<wmma::matrix_b, 16, 16, 16, __nv_bfloat16,
                           wmma::col_major> bh[2], bl[2];
            #pragma unroll
            for (int i = 0; i < 4; i++) {
                wmma::load_matrix_sync(ah[i],
                    sAh + (wm * 64 + i * 16) * LDS_ + kk, LDS_);
                wmma::load_matrix_sync(al[i],
                    sAl + (wm * 64 + i * 16) * LDS_ + kk, LDS_);
            }
            #pragma unroll
            for (int j = 0; j < 2; j++) {
                wmma::load_matrix_sync(bh[j],
                    sBh + (wn * 32 + j * 16) * LDS_ + kk, LDS_);
                wmma::load_matrix_sync(bl[j],
                    sBl + (wn * 32 + j * 16) * LDS_ + kk, LDS_);
            }
            #pragma unroll
            for (int i = 0; i < 4; i++)
                #pragma unroll
                for (int j = 0; j < 2; j++) {
                    wmma::mma_sync(acc[i][j], ah[i], bh[j], acc[i][j]);
                    wmma::mma_sync(acc[i][j], ah[i], bl[j], acc[i][j]);
                    wmma::mma_sync(acc[i][j], al[i], bh[j], acc[i][j]);
                }
        }
    }

    // epilogue: acc -> smem fp32 (ld 132) -> coalesced global
    __syncthreads();
    float* sf = (float*)smem;                 // 128 x 132 floats = 67584 B
    #pragma unroll
    for (int i = 0; i < 4; i++)
        #pragma unroll
        for (int j = 0; j < 2; j++)
            wmma::store_matrix_sync(
                sf + (wm * 64 + i * 16) * 132 + wn * 32 + j * 16,
                acc[i][j], 132, wmma::mem_row_major);
    __syncthreads();

    #pragma unroll 4
    for (int it = 0; it < 16; it++) {
        const int idx = tid + it * 256;       // 0..4095 float4s
        const int rr = idx >> 5;
        const int c4 = (idx & 31) * 4;
        float4 v = *(const float4*)&sf[rr * 132 + c4];
        const int m = mBase + rr;
        const int n = nBase + c4;
        if (EPI >= 1) {
            const float4 bi = *(const float4*)(bias + n);
            v.x += bi.x; v.y += bi.y; v.z += bi.z; v.w += bi.w;
        }
        if (EPI == 2) {
            v.x = gelu_tanh(v.x); v.y = gelu_tanh(v.y);
            v.z = gelu_tanh(v.z); v.w = gelu_tanh(v.w);
            split_store4(Chi, Clo, (size_t)m * N + n, v.x, v.y, v.z, v.w);
        } else {
            if (EPI == 1) {
                const float4 rv = *(const float4*)(res + (size_t)m * N + n);
                v.x += rv.x; v.y += rv.y; v.z += rv.z; v.w += rv.w;
            }
            *(float4*)(C + (size_t)m * N + n) = v;
        }
    }
}

// ---------------------------------------------------------------------------
// Flash attention (fp32, online softmax) -> bf16 hi/lo output
// ---------------------------------------------------------------------------
#define FA_STRIDE 68
#define FA_BUF (64 * FA_STRIDE)
#define FA_SMEM (4 * FA_BUF * 4)

__global__ __launch_bounds__(256) void flash_attn_k(
    const float* __restrict__ qkv,
    __nv_bfloat16* __restrict__ ohi, __nv_bfloat16* __restrict__ olo)
{
    extern __shared__ float sm[];
    float* Qt = sm;
    float* Kt = Qt + FA_BUF;
    float* Vs = Kt + FA_BUF;
    float* Ps = Vs + FA_BUF;

    const int b = blockIdx.z;
    const int h = blockIdx.y;
    const int qb = blockIdx.x * 64;
    const int t = threadIdx.x;
    const int tm = t >> 4;
    const int tn = t & 15;

    for (int idx = t; idx < 64 * 16; idx += 256) {
        const int m = idx >> 4;
        const int d4 = (idx & 15) * 4;
        const float4 v = *(const float4*)(
            qkv + (size_t)(b * L_ + qb + m) * (3 * D_) + h * HD_ + d4);
        Qt[(d4 + 0) * FA_STRIDE + m] = v.x;
        Qt[(d4 + 1) * FA_STRIDE + m] = v.y;
        Qt[(d4 + 2) * FA_STRIDE + m] = v.z;
        Qt[(d4 + 3) * FA_STRIDE + m] = v.w;
    }

    float mo[4] = {-INFINITY, -INFINITY, -INFINITY, -INFINITY};
    float lo[4] = {0.f, 0.f, 0.f, 0.f};
    float acc[4][4];
    #pragma unroll
    for (int i = 0; i < 4; i++)
        #pragma unroll
        for (int j = 0; j < 4; j++) acc[i][j] = 0.f;

    __syncthreads();

    for (int kb = 0; kb < L_; kb += 64) {
        for (int idx = t; idx < 64 * 16; idx += 256) {
            const int n = idx >> 4;
            const int d4 = (idx & 15) * 4;
            const float* kp = qkv + (size_t)(b * L_ + kb + n) * (3 * D_)
                              + D_ + h * HD_ + d4;
            const float4 kv = *(const float4*)kp;
            Kt[(d4 + 0) * FA_STRIDE + n] = kv.x;
            Kt[(d4 + 1) * FA_STRIDE + n] = kv.y;
            Kt[(d4 + 2) * FA_STRIDE + n] = kv.z;
            Kt[(d4 + 3) * FA_STRIDE + n] = kv.w;
            *(float4*)&Vs[n * FA_STRIDE + d4] = *(const float4*)(kp + D_);
        }
        __syncthreads();

        float s[4][4];
        #pragma unroll
        for (int i = 0; i < 4; i++)
            #pragma unroll
            for (int j = 0; j < 4; j++) s[i][j] = 0.f;
        #pragma unroll 4
        for (int k = 0; k < HD_; k++) {
            const float4 q4 = *(const float4*)&Qt[k * FA_STRIDE + tm * 4];
            const float4 k4 = *(const float4*)&Kt[k * FA_STRIDE + tn * 4];
            const float qr[4] = {q4.x, q4.y, q4.z, q4.w};
            const float kr[4] = {k4.x, k4.y, k4.z, k4.w};
            #pragma unroll
            for (int i = 0; i < 4; i++)
                #pragma unroll
                for (int j = 0; j < 4; j++)
                    s[i][j] = fmaf(qr[i], kr[j], s[i][j]);
        }

        #pragma unroll
        for (int i = 0; i < 4; i++) {
            float tmax = -INFINITY;
            #pragma unroll
            for (int j = 0; j < 4; j++) {
                s[i][j] *= 0.125f;
                tmax = fmaxf(tmax, s[i][j]);
            }
            #pragma unroll
            for (int off = 8; off > 0; off >>= 1)
                tmax = fmaxf(tmax, __shfl_xor_sync(0xffffffffu, tmax, off));

            const float mnew = fmaxf(mo[i], tmax);
            const float corr = __expf(mo[i] - mnew);
            float rs = 0.f;
            #pragma unroll
            for (int j = 0; j < 4; j++) {
                const float p = __expf(s[i][j] - mnew);
                Ps[(tm * 4 + i) * FA_STRIDE + tn * 4 + j] = p;
                rs += p;
            }
            #pragma unroll
            for (int off = 8; off > 0; off >>= 1)
                rs += __shfl_xor_sync(0xffffffffu, rs, off);

            lo[i] = lo[i] * corr + rs;
            mo[i] = mnew;
            #pragma unroll
            for (int j = 0; j < 4; j++) acc[i][j] *= corr;
        }
        __syncthreads();

        #pragma unroll 4
        for (int kk = 0; kk < 64; kk++) {
            const float4 v4 = *(const float4*)&Vs[kk * FA_STRIDE + tn * 4];
            const float vr[4] = {v4.x, v4.y, v4.z, v4.w};
            #pragma unroll
            for (int i = 0; i < 4; i++) {
                const float p = Ps[(tm * 4 + i) * FA_STRIDE + kk];
                #pragma unroll
                for (int j = 0; j < 4; j++)
                    acc[i][j] = fmaf(p, vr[j], acc[i][j]);
            }
        }
        __syncthreads();
    }

    #pragma unroll
    for (int i = 0; i < 4; i++) {
        const float inv = 1.0f / lo[i];
        split_store4(ohi, olo,
                     (size_t)(b * L_ + qb + tm * 4 + i) * D_ + h * HD_ + tn * 4,
                     acc[i][0] * inv, acc[i][1] * inv,
                     acc[i][2] * inv, acc[i][3] * inv);
    }
}

// ---------------------------------------------------------------------------
// Launch
// ---------------------------------------------------------------------------
extern "C" void kernel_launch(void* const* d_in, const int* in_sizes, int n_in,
                              void* d_out, int out_size)
{
    const float* x      = (const float*)d_in[0];
    const float* ln1_s  = (const float*)d_in[1];
    const float* ln1_b  = (const float*)d_in[2];
    const float* w_qkv  = (const float*)d_in[3];
    const float* w_proj = (const float*)d_in[4];
    const float* b_proj = (const float*)d_in[5];
    const float* ln2_s  = (const float*)d_in[6];
    const float* ln2_b  = (const float*)d_in[7];
    const float* w_mlp1 = (const float*)d_in[8];
    const float* b_mlp1 = (const float*)d_in[9];
    const float* w_mlp2 = (const float*)d_in[10];
    const float* b_mlp2 = (const float*)d_in[11];
    float* out = (float*)d_out;

    __nv_bfloat16 *hhi, *hlo, *athi, *atlo, *midhi, *midlo;
    __nv_bfloat16 *wqh, *wql, *wph, *wpl, *w1h, *w1l, *w2h, *w2l;
    float *qkv, *x1;
    cudaGetSymbolAddress((void**)&hhi, g_h_hi);
    cudaGetSymbolAddress((void**)&hlo, g_h_lo);
    cudaGetSymbolAddress((void**)&qkv, g_qkv);
    cudaGetSymbolAddress((void**)&athi, g_at_hi);
    cudaGetSymbolAddress((void**)&atlo, g_at_lo);
    cudaGetSymbolAddress((void**)&x1, g_x1);
    cudaGetSymbolAddress((void**)&midhi, g_mid_hi);
    cudaGetSymbolAddress((void**)&midlo, g_mid_lo);
    cudaGetSymbolAddress((void**)&wqh, g_wqkv_hi);
    cudaGetSymbolAddress((void**)&wql, g_wqkv_lo);
    cudaGetSymbolAddress((void**)&wph, g_wpr_hi);
    cudaGetSymbolAddress((void**)&wpl, g_wpr_lo);
    cudaGetSymbolAddress((void**)&w1h, g_wm1_hi);
    cudaGetSymbolAddress((void**)&w1l, g_wm1_lo);
    cudaGetSymbolAddress((void**)&w2h, g_wm2_hi);
    cudaGetSymbolAddress((void**)&w2l, g_wm2_lo);

    static bool attr_set = false;
    if (!attr_set) {
        cudaFuncSetAttribute(flash_attn_k,
            cudaFuncAttributeMaxDynamicSharedMemorySize, FA_SMEM);
        cudaFuncSetAttribute(wm_gemm<0>,
            cudaFuncAttributeMaxDynamicSharedMemorySize, GEMM_SMEM);
        cudaFuncSetAttribute(wm_gemm<1>,
            cudaFuncAttributeMaxDynamicSharedMemorySize, GEMM_SMEM);
        cudaFuncSetAttribute(wm_gemm<2>,
            cudaFuncAttributeMaxDynamicSharedMemorySize, GEMM_SMEM);
        attr_set = true;
    }

    const dim3 tb(32, 8);
    // weight transpose + bf16 split (per launch; deterministic)
    wsplit_t<<<dim3(3 * D_ / 32, D_ / 32), tb>>>(w_qkv, wqh, wql, D_, 3 * D_);
    wsplit_t<<<dim3(D_ / 32, D_ / 32), tb>>>(w_proj, wph, wpl, D_, D_);
    wsplit_t<<<dim3(F_ / 32, D_ / 32), tb>>>(w_mlp1, w1h, w1l, D_, F_);
    wsplit_t<<<dim3(D_ / 32, F_ / 32), tb>>>(w_mlp2, w2h, w2l, F_, D_);

    // 1) pre-norm 1 -> bf16 hi/lo
    layernorm_k<<<M_, 256>>>(x, ln1_s, ln1_b, hhi, hlo);
    // 2) qkv projection -> fp32
    wm_gemm<0><<<dim3(3 * D_ / BN, M_ / BM), 256, GEMM_SMEM>>>(
        hhi, hlo, wqh, wql, nullptr, nullptr, qkv, nullptr, nullptr,
        M_, 3 * D_, D_);
    // 3) attention -> bf16 hi/lo
    flash_attn_k<<<dim3(L_ / 64, H_, B_), 256, FA_SMEM>>>(qkv, athi, atlo);
    // 4) out proj + bias + residual -> fp32 x1
    wm_gemm<1><<<dim3(D_ / BN, M_ / BM), 256, GEMM_SMEM>>>(
        athi, atlo, wph, wpl, b_proj, x, x1, nullptr, nullptr,
        M_, D_, D_);
    // 5) pre-norm 2 -> bf16 hi/lo
    layernorm_k<<<M_, 256>>>(x1, ln2_s, ln2_b, hhi, hlo);
    // 6) MLP up + bias + gelu -> bf16 hi/lo
    wm_gemm<2><<<dim3(F_ / BN, M_ / BM), 256, GEMM_SMEM>>>(
        hhi, hlo, w1h, w1l, b_mlp1, nullptr, nullptr, midhi, midlo,
        M_, F_, D_);
    // 7) MLP down + bias + residual -> final out
    wm_gemm<1><<<dim3(D_ / BN, M_ / BM), 256, GEMM_SMEM>>>(
        midhi, midlo, w2h, w2l, b_mlp2, x1, out, nullptr, nullptr,
        M_, D_, F_);
}

// round 9
// speedup vs baseline: 1.6488x; 1.0969x over previous
#include <cuda_runtime.h>
#include <cuda_bf16.h>
#include <mma.h>
#include <math.h>
#include <stdint.h>

using namespace nvcuda;

// Problem constants
#define B_ 2
#define L_ 2048
#define D_ 1024
#define F_ 4096
#define H_ 16
#define HD_ 64
#define M_ (B_ * L_)
#define LN_EPS 1e-6f

// ---------------------------------------------------------------------------
// Scratch (static device globals; no allocation anywhere)
// ---------------------------------------------------------------------------
__device__ __nv_bfloat16 g_h_hi[M_ * D_];
__device__ __nv_bfloat16 g_h_lo[M_ * D_];
__device__ float         g_qkv[M_ * 3 * D_];
__device__ __nv_bfloat16 g_at_hi[M_ * D_];
__device__ __nv_bfloat16 g_at_lo[M_ * D_];
__device__ float         g_x1[M_ * D_];
__device__ __nv_bfloat16 g_mid_hi[M_ * F_];
__device__ __nv_bfloat16 g_mid_lo[M_ * F_];
// weights transposed to [N][K], split hi/lo
__device__ __nv_bfloat16 g_wqkv_hi[3 * D_ * D_];
__device__ __nv_bfloat16 g_wqkv_lo[3 * D_ * D_];
__device__ __nv_bfloat16 g_wpr_hi[D_ * D_];
__device__ __nv_bfloat16 g_wpr_lo[D_ * D_];
__device__ __nv_bfloat16 g_wm1_hi[F_ * D_];
__device__ __nv_bfloat16 g_wm1_lo[F_ * D_];
__device__ __nv_bfloat16 g_wm2_hi[D_ * F_];
__device__ __nv_bfloat16 g_wm2_lo[D_ * F_];

// ---------------------------------------------------------------------------
// helpers
// ---------------------------------------------------------------------------
__device__ __forceinline__ uint32_t smem_to_u32(const void* p) {
    uint32_t a;
    asm("{ .reg .u64 t; cvta.to.shared.u64 t, %1; cvt.u32.u64 %0, t; }"
        : "=r"(a) : "l"(p));
    return a;
}

__device__ __forceinline__ void cp16(uint32_t daddr, const void* g) {
    asm volatile("cp.async.cg.shared.global [%0], [%1], 16;"
                 :: "r"(daddr), "l"(g));
}
#define CP_COMMIT() asm volatile("cp.async.commit_group;" ::: "memory")
#define CP_WAIT_ALL() asm volatile("cp.async.wait_group 0;" ::: "memory")

__device__ __forceinline__ uint32_t bf2u(__nv_bfloat16 a, __nv_bfloat16 b) {
    return (uint32_t)__bfloat16_as_ushort(a) |
           ((uint32_t)__bfloat16_as_ushort(b) << 16);
}

__device__ __forceinline__ void split_store4(
    __nv_bfloat16* __restrict__ hi, __nv_bfloat16* __restrict__ lo,
    size_t off, float a, float b, float c, float d)
{
    __nv_bfloat16 h0 = __float2bfloat16(a), h1 = __float2bfloat16(b);
    __nv_bfloat16 h2 = __float2bfloat16(c), h3 = __float2bfloat16(d);
    __nv_bfloat16 l0 = __float2bfloat16(a - __bfloat162float(h0));
    __nv_bfloat16 l1 = __float2bfloat16(b - __bfloat162float(h1));
    __nv_bfloat16 l2 = __float2bfloat16(c - __bfloat162float(h2));
    __nv_bfloat16 l3 = __float2bfloat16(d - __bfloat162float(h3));
    *(uint2*)(hi + off) = make_uint2(bf2u(h0, h1), bf2u(h2, h3));
    *(uint2*)(lo + off) = make_uint2(bf2u(l0, l1), bf2u(l2, l3));
}

__device__ __forceinline__ float gelu_tanh(float v) {
    const float c = 0.7978845608028654f;
    float u = c * (v + 0.044715f * v * v * v);
    return 0.5f * v * (1.0f + tanhf(u));
}

// ---------------------------------------------------------------------------
// Weight transpose + split: W[K][N] -> hi/lo[N][K] bf16
// ---------------------------------------------------------------------------
__global__ __launch_bounds__(256) void wsplit_t(
    const float* __restrict__ W, __nv_bfloat16* __restrict__ hi,
    __nv_bfloat16* __restrict__ lo, int K, int N)
{
    __shared__ float t[32][33];
    const int n0 = blockIdx.x * 32, k0 = blockIdx.y * 32;
    const int tx = threadIdx.x, ty = threadIdx.y;
    #pragma unroll
    for (int i = ty; i < 32; i += 8)
        t[i][tx] = W[(size_t)(k0 + i) * N + n0 + tx];
    __syncthreads();
    #pragma unroll
    for (int i = ty; i < 32; i += 8) {
        const float v = t[tx][i];                 // W[k0+tx][n0+i]
        const __nv_bfloat16 h = __float2bfloat16(v);
        const __nv_bfloat16 l = __float2bfloat16(v - __bfloat162float(h));
        const size_t o = (size_t)(n0 + i) * K + k0 + tx;
        hi[o] = h; lo[o] = l;
    }
}

// ---------------------------------------------------------------------------
// LayerNorm -> bf16 hi/lo
// ---------------------------------------------------------------------------
__global__ __launch_bounds__(256) void layernorm_k(
    const float* __restrict__ x, const float* __restrict__ gamma,
    const float* __restrict__ beta,
    __nv_bfloat16* __restrict__ ohi, __nv_bfloat16* __restrict__ olo)
{
    const int row = blockIdx.x;
    const int t = threadIdx.x;
    const float4 v = *(const float4*)(x + (size_t)row * D_ + t * 4);

    float s = v.x + v.y + v.z + v.w;
    float q = v.x * v.x + v.y * v.y + v.z * v.z + v.w * v.w;
    #pragma unroll
    for (int off = 16; off > 0; off >>= 1) {
        s += __shfl_down_sync(0xffffffffu, s, off);
        q += __shfl_down_sync(0xffffffffu, q, off);
    }
    __shared__ float ss[8], qq[8];
    const int wid = t >> 5, lane = t & 31;
    if (lane == 0) { ss[wid] = s; qq[wid] = q; }
    __syncthreads();
    if (t == 0) {
        float S = 0.f, Q = 0.f;
        #pragma unroll
        for (int i = 0; i < 8; i++) { S += ss[i]; Q += qq[i]; }
        ss[0] = S; qq[0] = Q;
    }
    __syncthreads();
    const float mu = ss[0] * (1.0f / D_);
    const float var = qq[0] * (1.0f / D_) - mu * mu;
    const float rstd = rsqrtf(var + LN_EPS);

    const float4 g4 = *(const float4*)(gamma + t * 4);
    const float4 b4 = *(const float4*)(beta + t * 4);
    const float ox = (v.x - mu) * rstd * g4.x + b4.x;
    const float oy = (v.y - mu) * rstd * g4.y + b4.y;
    const float oz = (v.z - mu) * rstd * g4.z + b4.z;
    const float ow = (v.w - mu) * rstd * g4.w + b4.w;
    split_store4(ohi, olo, (size_t)row * D_ + t * 4, ox, oy, oz, ow);
}

// ---------------------------------------------------------------------------
// WMMA GEMM: C[M,N] = (Ahi+Alo)[M,K] @ (Bhi+Blo)[N,K]^T  (bf16x3, fp32 acc)
// 128x256 CTA tile, BK=32, 256 threads (8 warps 2x4, warp tile 64x64),
// cp.async 2-stage double buffer.
// EPI: 0 = fp32 out, 1 = +bias +residual -> fp32, 2 = +bias +gelu -> bf16 hi/lo
// ---------------------------------------------------------------------------
#define BM 128
#define BN 256
#define BK 32
#define LDS_ 40                          // bf16 ld (elements): 80B rows (16B mult)
#define A_EL (128 * LDS_)                // 5120 elems per A tile
#define B_EL (256 * LDS_)                // 10240 elems per B tile
#define STAGE_EL (2 * A_EL + 2 * B_EL)   // Ahi, Alo, Bhi, Blo = 30720 elems
#define EPI_LD 260                       // fp32 epilogue ld (1040B, 16B mult)
#define GEMM_SMEM (BM * EPI_LD * 4)      // 133120 B (covers 2*STAGE_EL*2=122880)

template <int EPI>
__global__ __launch_bounds__(256, 1) void wm_gemm(
    const __nv_bfloat16* __restrict__ Ahi, const __nv_bfloat16* __restrict__ Alo,
    const __nv_bfloat16* __restrict__ Bhi, const __nv_bfloat16* __restrict__ Blo,
    const float* __restrict__ bias, const float* __restrict__ res,
    float* __restrict__ C, __nv_bfloat16* __restrict__ Chi,
    __nv_bfloat16* __restrict__ Clo, int M, int N, int K)
{
    extern __shared__ char smem[];
    __nv_bfloat16* sb = (__nv_bfloat16*)smem;
    const uint32_t sbase = smem_to_u32(smem);
    const int tid = threadIdx.x;
    const int w = tid >> 5;
    const int wm = w >> 2;                // 0..1  (64-row slab)
    const int wn = w & 3;                 // 0..3  (64-col slab)
    const int mBase = blockIdx.y * BM;
    const int nBase = blockIdx.x * BN;

    // loader units: Ahi(128 rows), Alo(128), Bhi(256), Blo(256)
    const __nv_bfloat16* gsrc[4] = {
        Ahi + (size_t)mBase * K,
        Alo + (size_t)mBase * K,
        Bhi + (size_t)nBase * K,
        Blo + (size_t)nBase * K };
    const int unit_of_it[12]  = {0,0, 1,1, 2,2,2,2, 3,3,3,3};
    const int rbase_of_it[12] = {0,0, 128,128, 256,256,256,256, 512,512,512,512};
    const int soff_of_unit[4] = {0, A_EL, 2 * A_EL, 2 * A_EL + B_EL};

    wmma::fragment<wmma::accumulator, 16, 16, 16, float> acc[4][4];
    #pragma unroll
    for (int i = 0; i < 4; i++)
        #pragma unroll
        for (int j = 0; j < 4; j++)
            wmma::fill_fragment(acc[i][j], 0.0f);

    const int nchunks = K / BK;

    // stage loader: 768 rows x 32 bf16 = 3072 16B copies = 12 per thread
    auto load_stage = [&](int stg, int k0) {
        const uint32_t so = sbase + (uint32_t)stg * STAGE_EL * 2;
        #pragma unroll
        for (int it = 0; it < 12; it++) {
            const int idx = it * 256 + tid;           // 0..3071
            const int r = idx >> 2;                   // global row 0..767
            const int seg = idx & 3;                  // 16B segment
            const int u = unit_of_it[it];
            const int lr = r - rbase_of_it[it];
            cp16(so + (uint32_t)(soff_of_unit[u] + lr * LDS_ + seg * 8) * 2,
                 gsrc[u] + (size_t)lr * K + k0 + seg * 8);
        }
    };

    load_stage(0, 0);
    CP_COMMIT();

    for (int c = 0; c < nchunks; c++) {
        CP_WAIT_ALL();
        __syncthreads();
        if (c + 1 < nchunks) {
            load_stage((c + 1) & 1, (c + 1) * BK);
            CP_COMMIT();
        }
        const __nv_bfloat16* st = sb + (c & 1) * STAGE_EL;
        const __nv_bfloat16* sAh = st;
        const __nv_bfloat16* sAl = st + A_EL;
        const __nv_bfloat16* sBh = st + 2 * A_EL;
        const __nv_bfloat16* sBl = st + 2 * A_EL + B_EL;

        #pragma unroll
        for (int kk = 0; kk < BK; kk += 16) {
            wmma::fragment<wmma::matrix_b, 16, 16, 16, __nv_bfloat16,
                           wmma::col_major> bh[4], bl[4];
            #pragma unroll
            for (int j = 0; j < 4; j++) {
                wmma::load_matrix_sync(bh[j],
                    sBh + (wn * 64 + j * 16) * LDS_ + kk, LDS_);
                wmma::load_matrix_sync(bl[j],
                    sBl + (wn * 64 + j * 16) * LDS_ + kk, LDS_);
            }
            #pragma unroll
            for (int i = 0; i < 4; i++) {
                wmma::fragment<wmma::matrix_a, 16, 16, 16, __nv_bfloat16,
                               wmma::row_major> ah, al;
                wmma::load_matrix_sync(ah,
                    sAh + (wm * 64 + i * 16) * LDS_ + kk, LDS_);
                wmma::load_matrix_sync(al,
                    sAl + (wm * 64 + i * 16) * LDS_ + kk, LDS_);
                #pragma unroll
                for (int j = 0; j < 4; j++) {
                    wmma::mma_sync(acc[i][j], ah, bh[j], acc[i][j]);
                    wmma::mma_sync(acc[i][j], ah, bl[j], acc[i][j]);
                    wmma::mma_sync(acc[i][j], al, bh[j], acc[i][j]);
                }
            }
        }
    }

    // epilogue: acc -> smem fp32 (ld EPI_LD) -> coalesced global
    __syncthreads();
    float* sf = (float*)smem;                 // 128 x 260 floats
    #pragma unroll
    for (int i = 0; i < 4; i++)
        #pragma unroll
        for (int j = 0; j < 4; j++)
            wmma::store_matrix_sync(
                sf + (wm * 64 + i * 16) * EPI_LD + wn * 64 + j * 16,
                acc[i][j], EPI_LD, wmma::mem_row_major);
    __syncthreads();

    #pragma unroll 4
    for (int it = 0; it < 32; it++) {
        const int idx = tid + it * 256;       // 0..8191 float4s
        const int rr = idx >> 6;
        const int c4 = (idx & 63) * 4;
        float4 v = *(const float4*)&sf[rr * EPI_LD + c4];
        const int m = mBase + rr;
        const int n = nBase + c4;
        if (EPI >= 1) {
            const float4 bi = *(const float4*)(bias + n);
            v.x += bi.x; v.y += bi.y; v.z += bi.z; v.w += bi.w;
        }
        if (EPI == 2) {
            v.x = gelu_tanh(v.x); v.y = gelu_tanh(v.y);
            v.z = gelu_tanh(v.z); v.w = gelu_tanh(v.w);
            split_store4(Chi, Clo, (size_t)m * N + n, v.x, v.y, v.z, v.w);
        } else {
            if (EPI == 1) {
                const float4 rv = *(const float4*)(res + (size_t)m * N + n);
                v.x += rv.x; v.y += rv.y; v.z += rv.z; v.w += rv.w;
            }
            *(float4*)(C + (size_t)m * N + n) = v;
        }
    }
}

// ---------------------------------------------------------------------------
// Flash attention (fp32, online softmax) -> bf16 hi/lo output
// ---------------------------------------------------------------------------
#define FA_STRIDE 68
#define FA_BUF (64 * FA_STRIDE)
#define FA_SMEM (4 * FA_BUF * 4)

__global__ __launch_bounds__(256) void flash_attn_k(
    const float* __restrict__ qkv,
    __nv_bfloat16* __restrict__ ohi, __nv_bfloat16* __restrict__ olo)
{
    extern __shared__ float sm[];
    float* Qt = sm;
    float* Kt = Qt + FA_BUF;
    float* Vs = Kt + FA_BUF;
    float* Ps = Vs + FA_BUF;

    const int b = blockIdx.z;
    const int h = blockIdx.y;
    const int qb = blockIdx.x * 64;
    const int t = threadIdx.x;
    const int tm = t >> 4;
    const int tn = t & 15;

    for (int idx = t; idx < 64 * 16; idx += 256) {
        const int m = idx >> 4;
        const int d4 = (idx & 15) * 4;
        const float4 v = *(const float4*)(
            qkv + (size_t)(b * L_ + qb + m) * (3 * D_) + h * HD_ + d4);
        Qt[(d4 + 0) * FA_STRIDE + m] = v.x;
        Qt[(d4 + 1) * FA_STRIDE + m] = v.y;
        Qt[(d4 + 2) * FA_STRIDE + m] = v.z;
        Qt[(d4 + 3) * FA_STRIDE + m] = v.w;
    }

    float mo[4] = {-INFINITY, -INFINITY, -INFINITY, -INFINITY};
    float lo[4] = {0.f, 0.f, 0.f, 0.f};
    float acc[4][4];
    #pragma unroll
    for (int i = 0; i < 4; i++)
        #pragma unroll
        for (int j = 0; j < 4; j++) acc[i][j] = 0.f;

    __syncthreads();

    for (int kb = 0; kb < L_; kb += 64) {
        for (int idx = t; idx < 64 * 16; idx += 256) {
            const int n = idx >> 4;
            const int d4 = (idx & 15) * 4;
            const float* kp = qkv + (size_t)(b * L_ + kb + n) * (3 * D_)
                              + D_ + h * HD_ + d4;
            const float4 kv = *(const float4*)kp;
            Kt[(d4 + 0) * FA_STRIDE + n] = kv.x;
            Kt[(d4 + 1) * FA_STRIDE + n] = kv.y;
            Kt[(d4 + 2) * FA_STRIDE + n] = kv.z;
            Kt[(d4 + 3) * FA_STRIDE + n] = kv.w;
            *(float4*)&Vs[n * FA_STRIDE + d4] = *(const float4*)(kp + D_);
        }
        __syncthreads();

        float s[4][4];
        #pragma unroll
        for (int i = 0; i < 4; i++)
            #pragma unroll
            for (int j = 0; j < 4; j++) s[i][j] = 0.f;
        #pragma unroll 4
        for (int k = 0; k < HD_; k++) {
            const float4 q4 = *(const float4*)&Qt[k * FA_STRIDE + tm * 4];
            const float4 k4 = *(const float4*)&Kt[k * FA_STRIDE + tn * 4];
            const float qr[4] = {q4.x, q4.y, q4.z, q4.w};
            const float kr[4] = {k4.x, k4.y, k4.z, k4.w};
            #pragma unroll
            for (int i = 0; i < 4; i++)
                #pragma unroll
                for (int j = 0; j < 4; j++)
                    s[i][j] = fmaf(qr[i], kr[j], s[i][j]);
        }

        #pragma unroll
        for (int i = 0; i < 4; i++) {
            float tmax = -INFINITY;
            #pragma unroll
            for (int j = 0; j < 4; j++) {
                s[i][j] *= 0.125f;
                tmax = fmaxf(tmax, s[i][j]);
            }
            #pragma unroll
            for (int off = 8; off > 0; off >>= 1)
                tmax = fmaxf(tmax, __shfl_xor_sync(0xffffffffu, tmax, off));

            const float mnew = fmaxf(mo[i], tmax);
            const float corr = __expf(mo[i] - mnew);
            float rs = 0.f;
            #pragma unroll
            for (int j = 0; j < 4; j++) {
                const float p = __expf(s[i][j] - mnew);
                Ps[(tm * 4 + i) * FA_STRIDE + tn * 4 + j] = p;
                rs += p;
            }
            #pragma unroll
            for (int off = 8; off > 0; off >>= 1)
                rs += __shfl_xor_sync(0xffffffffu, rs, off);

            lo[i] = lo[i] * corr + rs;
            mo[i] = mnew;
            #pragma unroll
            for (int j = 0; j < 4; j++) acc[i][j] *= corr;
        }
        __syncthreads();

        #pragma unroll 4
        for (int kk = 0; kk < 64; kk++) {
            const float4 v4 = *(const float4*)&Vs[kk * FA_STRIDE + tn * 4];
            const float vr[4] = {v4.x, v4.y, v4.z, v4.w};
            #pragma unroll
            for (int i = 0; i < 4; i++) {
                const float p = Ps[(tm * 4 + i) * FA_STRIDE + kk];
                #pragma unroll
                for (int j = 0; j < 4; j++)
                    acc[i][j] = fmaf(p, vr[j], acc[i][j]);
            }
        }
        __syncthreads();
    }

    #pragma unroll
    for (int i = 0; i < 4; i++) {
        const float inv = 1.0f / lo[i];
        split_store4(ohi, olo,
                     (size_t)(b * L_ + qb + tm * 4 + i) * D_ + h * HD_ + tn * 4,
                     acc[i][0] * inv, acc[i][1] * inv,
                     acc[i][2] * inv, acc[i][3] * inv);
    }
}

// ---------------------------------------------------------------------------
// Launch
// ---------------------------------------------------------------------------
extern "C" void kernel_launch(void* const* d_in, const int* in_sizes, int n_in,
                              void* d_out, int out_size)
{
    const float* x      = (const float*)d_in[0];
    const float* ln1_s  = (const float*)d_in[1];
    const float* ln1_b  = (const float*)d_in[2];
    const float* w_qkv  = (const float*)d_in[3];
    const float* w_proj = (const float*)d_in[4];
    const float* b_proj = (const float*)d_in[5];
    const float* ln2_s  = (const float*)d_in[6];
    const float* ln2_b  = (const float*)d_in[7];
    const float* w_mlp1 = (const float*)d_in[8];
    const float* b_mlp1 = (const float*)d_in[9];
    const float* w_mlp2 = (const float*)d_in[10];
    const float* b_mlp2 = (const float*)d_in[11];
    float* out = (float*)d_out;

    __nv_bfloat16 *hhi, *hlo, *athi, *atlo, *midhi, *midlo;
    __nv_bfloat16 *wqh, *wql, *wph, *wpl, *w1h, *w1l, *w2h, *w2l;
    float *qkv, *x1;
    cudaGetSymbolAddress((void**)&hhi, g_h_hi);
    cudaGetSymbolAddress((void**)&hlo, g_h_lo);
    cudaGetSymbolAddress((void**)&qkv, g_qkv);
    cudaGetSymbolAddress((void**)&athi, g_at_hi);
    cudaGetSymbolAddress((void**)&atlo, g_at_lo);
    cudaGetSymbolAddress((void**)&x1, g_x1);
    cudaGetSymbolAddress((void**)&midhi, g_mid_hi);
    cudaGetSymbolAddress((void**)&midlo, g_mid_lo);
    cudaGetSymbolAddress((void**)&wqh, g_wqkv_hi);
    cudaGetSymbolAddress((void**)&wql, g_wqkv_lo);
    cudaGetSymbolAddress((void**)&wph, g_wpr_hi);
    cudaGetSymbolAddress((void**)&wpl, g_wpr_lo);
    cudaGetSymbolAddress((void**)&w1h, g_wm1_hi);
    cudaGetSymbolAddress((void**)&w1l, g_wm1_lo);
    cudaGetSymbolAddress((void**)&w2h, g_wm2_hi);
    cudaGetSymbolAddress((void**)&w2l, g_wm2_lo);

    static bool attr_set = false;
    if (!attr_set) {
        cudaFuncSetAttribute(flash_attn_k,
            cudaFuncAttributeMaxDynamicSharedMemorySize, FA_SMEM);
        cudaFuncSetAttribute(wm_gemm<0>,
            cudaFuncAttributeMaxDynamicSharedMemorySize, GEMM_SMEM);
        cudaFuncSetAttribute(wm_gemm<1>,
            cudaFuncAttributeMaxDynamicSharedMemorySize, GEMM_SMEM);
        cudaFuncSetAttribute(wm_gemm<2>,
            cudaFuncAttributeMaxDynamicSharedMemorySize, GEMM_SMEM);
        attr_set = true;
    }

    const dim3 tb(32, 8);
    // weight transpose + bf16 split (per launch; deterministic)
    wsplit_t<<<dim3(3 * D_ / 32, D_ / 32), tb>>>(w_qkv, wqh, wql, D_, 3 * D_);
    wsplit_t<<<dim3(D_ / 32, D_ / 32), tb>>>(w_proj, wph, wpl, D_, D_);
    wsplit_t<<<dim3(F_ / 32, D_ / 32), tb>>>(w_mlp1, w1h, w1l, D_, F_);
    wsplit_t<<<dim3(D_ / 32, F_ / 32), tb>>>(w_mlp2, w2h, w2l, F_, D_);

    // 1) pre-norm 1 -> bf16 hi/lo
    layernorm_k<<<M_, 256>>>(x, ln1_s, ln1_b, hhi, hlo);
    // 2) qkv projection -> fp32
    wm_gemm<0><<<dim3(3 * D_ / BN, M_ / BM), 256, GEMM_SMEM>>>(
        hhi, hlo, wqh, wql, nullptr, nullptr, qkv, nullptr, nullptr,
        M_, 3 * D_, D_);
    // 3) attention -> bf16 hi/lo
    flash_attn_k<<<dim3(L_ / 64, H_, B_), 256, FA_SMEM>>>(qkv, athi, atlo);
    // 4) out proj + bias + residual -> fp32 x1
    wm_gemm<1><<<dim3(D_ / BN, M_ / BM), 256, GEMM_SMEM>>>(
        athi, atlo, wph, wpl, b_proj, x, x1, nullptr, nullptr,
        M_, D_, D_);
    // 5) pre-norm 2 -> bf16 hi/lo
    layernorm_k<<<M_, 256>>>(x1, ln2_s, ln2_b, hhi, hlo);
    // 6) MLP up + bias + gelu -> bf16 hi/lo
    wm_gemm<2><<<dim3(F_ / BN, M_ / BM), 256, GEMM_SMEM>>>(
        hhi, hlo, w1h, w1l, b_mlp1, nullptr, nullptr, midhi, midlo,
        M_, F_, D_);
    // 7) MLP down + bias + residual -> final out
    wm_gemm<1><<<dim3(D_ / BN, M_ / BM), 256, GEMM_SMEM>>>(
        midhi, midlo, w2h, w2l, b_mlp2, x1, out, nullptr, nullptr,
        M_, D_, F_);
}